// round 10
// baseline (speedup 1.0000x reference)
#include <cuda_runtime.h>
#include <math.h>

#define BATCH   4
#define NPTS    50000
#define GX      640
#define NC      (GX*GX)
#define MAXPIL  12000
#define MAXPT   100
#define TOTPTS  (BATCH*NPTS)
#define TOTCELL (BATCH*NC)
#define SCANTH  1024
#define CPT     (NC/SCANTH)

__device__ float4 g_pts[TOTPTS];
__device__ int    g_cid[TOTPTS];
__device__ int    g_cnt[TOTCELL];
__device__ int    g_off[TOTCELL];
__device__ int    g_sl[TOTCELL];
__device__ int    g_fl[TOTCELL];
__device__ int    g_lst[TOTPTS];

// f32(0.32f/102.4f) = 0.0031249998044222593f (0x3B4CCCCC)
__device__ __forceinline__ float whn_const() {
    return __fdiv_rn(__fmul_rn(2.0f, 0.16f), 102.4f);
}
// fl32(1 / WH_N) = 320.000030517578125f (0x43A00001)  [NOT 320.0f]
#define INV_WHN 320.000030517578125f

__global__ void k_clear() {
    int i = blockIdx.x * blockDim.x + threadIdx.x;
    int stride = gridDim.x * blockDim.x;
    for (; i < TOTCELL; i += stride) { g_cnt[i] = 0; g_fl[i] = 0; }
}

__global__ void k_pfill(float* po) {
    int i = blockIdx.x * blockDim.x + threadIdx.x;
    if (i < BATCH * MAXPIL) po[i] = -1.0f;   // float dtype, not int bits
}

__global__ void k_prep(const float* __restrict__ in) {
    int i = blockIdx.x * blockDim.x + threadIdx.x;
    if (i >= TOTPTS) return;
    float4 p = reinterpret_cast<const float4*>(in)[i];
    // XLA lowering: div-by-const -> mul by correctly-rounded f32 reciprocal.
    float xn = __fadd_rn(__fmul_rn(__fadd_rn(p.x, 51.2f), 0.01953125f), -1.0f);
    float yn = __fadd_rn(__fmul_rn(__fadd_rn(p.y, 51.2f), 0.01953125f), -1.0f);
    float zn = __fadd_rn(__fmul_rn(__fadd_rn(p.z,  5.0f), 0.25f),       -1.0f);
    float tx = __fmul_rn(__fadd_rn(xn, 1.0f), INV_WHN);
    float ty = __fmul_rn(__fadd_rn(yn, 1.0f), INV_WHN);
    int ix = (int)fminf(floorf(tx), 639.0f);
    int iy = (int)fminf(floorf(ty), 639.0f);
    ix = max(ix, 0); iy = max(iy, 0);
    int cell = iy * GX + ix;
    g_pts[i] = make_float4(xn, yn, zn, p.w);
    g_cid[i] = cell;
    int b = i / NPTS;
    atomicAdd(&g_cnt[b * NC + cell], 1);
}

__global__ void k_scan(float* __restrict__ pilOut, int hasPillar) {
    __shared__ int wsC[32], wsO[32];
    int b = blockIdx.x;
    int tid = threadIdx.x;
    int lane = tid & 31, warp = tid >> 5;
    int cbase = b * NC + tid * CPT;
    int sumC = 0, sumO = 0;
    for (int j = 0; j < CPT; j++) { int v = g_cnt[cbase + j]; sumC += v; sumO += (v > 0); }
    int sC = sumC, sO = sumO;
    for (int d = 1; d < 32; d <<= 1) {
        int aC = __shfl_up_sync(0xffffffffu, sC, d);
        int aO = __shfl_up_sync(0xffffffffu, sO, d);
        if (lane >= d) { sC += aC; sO += aO; }
    }
    if (lane == 31) { wsC[warp] = sC; wsO[warp] = sO; }
    __syncthreads();
    if (warp == 0) {
        int vC = wsC[lane], vO = wsO[lane];
        for (int d = 1; d < 32; d <<= 1) {
            int aC = __shfl_up_sync(0xffffffffu, vC, d);
            int aO = __shfl_up_sync(0xffffffffu, vO, d);
            if (lane >= d) { vC += aC; vO += aO; }
        }
        wsC[lane] = vC; wsO[lane] = vO;
    }
    __syncthreads();
    int exC = sC - sumC + (warp ? wsC[warp - 1] : 0);
    int exO = sO - sumO + (warp ? wsO[warp - 1] : 0);
    for (int j = 0; j < CPT; j++) {
        int c = cbase + j;
        int v = g_cnt[c];
        g_off[c] = exC;
        g_sl[c]  = exO;
        if (v > 0) {
            if (hasPillar && exO < MAXPIL)
                pilOut[b * MAXPIL + exO] = (float)(tid * CPT + j);   // float value
            exO++;
        }
        exC += v;
    }
}

__global__ void k_scat() {
    int i = blockIdx.x * blockDim.x + threadIdx.x;
    if (i >= TOTPTS) return;
    int b = i / NPTS;
    int c = b * NC + g_cid[i];
    int pos = g_off[c] + atomicAdd(&g_fl[c], 1);
    if (pos < NPTS) g_lst[b * NPTS + pos] = i - b * NPTS;
}

__global__ void k_emit(float* __restrict__ out) {
    int i = blockIdx.x * blockDim.x + threadIdx.x;
    if (i >= TOTPTS) return;
    int b  = i / NPTS;
    int li = i - b * NPTS;
    int cell = g_cid[i];
    int c = b * NC + cell;
    int slot = g_sl[c];
    if (slot >= MAXPIL) return;
    int n = g_cnt[c];
    int lb = b * NPTS + g_off[c];
    int pb = b * NPTS;
    int rank = 0;
    double sx = 0.0, sy = 0.0, sz = 0.0;
    for (int t = 0; t < n; t++) {
        int pj = g_lst[lb + t];
        rank += (pj < li);
        float4 q = g_pts[pb + pj];
        sx += (double)q.x; sy += (double)q.y; sz += (double)q.z;
    }
    if (rank >= MAXPT) return;
    double dn = (double)n;
    float mx = (float)(sx / dn);
    float my = (float)(sy / dn);
    float mz = (float)(sz / dn);
    float4 p = g_pts[i];
    const float WHN = whn_const();
    float cx = __fadd_rn(__fadd_rn(-1.0f, __fmul_rn((float)(cell % GX), WHN)), __fmul_rn(WHN, 0.5f));
    float cy = __fadd_rn(__fadd_rn(-1.0f, __fmul_rn((float)(cell / GX), WHN)), __fmul_rn(WHN, 0.5f));
    float* o = out + ((size_t)(b * MAXPIL + slot) * MAXPT + rank) * 9;
    o[0] = p.x; o[1] = p.y; o[2] = p.z; o[3] = p.w;
    o[4] = fabsf(__fadd_rn(p.x, -mx));
    o[5] = fabsf(__fadd_rn(p.y, -my));
    o[6] = fabsf(__fadd_rn(p.z, -mz));
    o[7] = __fadd_rn(cx, -p.x);
    o[8] = __fadd_rn(cy, -p.y);
}

extern "C" void kernel_launch(void* const* d_in, const int* in_sizes, int n_in,
                              void* d_out, int out_size) {
    const float* in = (const float*)d_in[0];
    float* out = (float*)d_out;
    const long long FEAT = (long long)BATCH * MAXPIL * MAXPT * 9;
    int hasPillar = ((long long)out_size >= FEAT + (long long)BATCH * MAXPIL);
    float* pilOut = out + FEAT;

    cudaMemsetAsync(d_out, 0, (size_t)out_size * sizeof(float), 0);
    k_clear<<<2048, 256>>>();
    if (hasPillar) k_pfill<<<(BATCH * MAXPIL + 255) / 256, 256>>>(pilOut);
    k_prep<<<(TOTPTS + 255) / 256, 256>>>(in);
    k_scan<<<BATCH, SCANTH>>>(pilOut, hasPillar);
    k_scat<<<(TOTPTS + 255) / 256, 256>>>();
    k_emit<<<(TOTPTS + 255) / 256, 256>>>(out);
}

// round 11
// speedup vs baseline: 1.6360x; 1.6360x over previous
#include <cuda_runtime.h>
#include <math.h>

#define BATCH   4
#define NPTS    50000
#define GX      640
#define NC      (GX*GX)
#define MAXPIL  12000
#define MAXPT   100
#define TOTPTS  (BATCH*NPTS)
#define TOTCELL (BATCH*NC)
#define SCANTH  1024
#define CPT     (NC/SCANTH)

__device__ float4 g_pts[TOTPTS];
__device__ int    g_cid[TOTPTS];
__device__ int    g_cnt[TOTCELL];
__device__ int    g_off[TOTCELL];
__device__ int    g_sl[TOTCELL];
__device__ int    g_fl[TOTCELL];
__device__ int    g_lst[TOTPTS];

// f32(0.32f/102.4f) = 0.0031249998044222593f (0x3B4CCCCC)
__device__ __forceinline__ float whn_const() {
    return __fdiv_rn(__fmul_rn(2.0f, 0.16f), 102.4f);
}
// fl32(1 / WH_N) = 320.000030517578125f (0x43A00001)
#define INV_WHN 320.000030517578125f

// Vectorized zero of the full output buffer (replaces the slow memset graph node).
__global__ void k_zfill(float4* __restrict__ o4, int n4, float* __restrict__ tail, int ntail) {
    int i = blockIdx.x * blockDim.x + threadIdx.x;
    int stride = gridDim.x * blockDim.x;
    float4 z = make_float4(0.f, 0.f, 0.f, 0.f);
    for (; i < n4; i += stride) o4[i] = z;
    if (blockIdx.x == 0 && threadIdx.x < ntail) tail[threadIdx.x] = 0.f;
}

// Scratch clears + pillar output fill, one small launch.
__global__ void k_aux(float* po, int hasPillar) {
    int i = blockIdx.x * blockDim.x + threadIdx.x;
    int stride = gridDim.x * blockDim.x;
    for (int j = i; j < TOTCELL; j += stride) { g_cnt[j] = 0; g_fl[j] = 0; }
    if (hasPillar)
        for (int j = i; j < BATCH * MAXPIL; j += stride) po[j] = -1.0f;
}

__global__ void k_prep(const float* __restrict__ in) {
    int i = blockIdx.x * blockDim.x + threadIdx.x;
    if (i >= TOTPTS) return;
    float4 p = reinterpret_cast<const float4*>(in)[i];
    // XLA lowering: div-by-const -> mul by correctly-rounded f32 reciprocal.
    float xn = __fadd_rn(__fmul_rn(__fadd_rn(p.x, 51.2f), 0.01953125f), -1.0f);
    float yn = __fadd_rn(__fmul_rn(__fadd_rn(p.y, 51.2f), 0.01953125f), -1.0f);
    float zn = __fadd_rn(__fmul_rn(__fadd_rn(p.z,  5.0f), 0.25f),       -1.0f);
    float tx = __fmul_rn(__fadd_rn(xn, 1.0f), INV_WHN);
    float ty = __fmul_rn(__fadd_rn(yn, 1.0f), INV_WHN);
    int ix = (int)fminf(floorf(tx), 639.0f);
    int iy = (int)fminf(floorf(ty), 639.0f);
    ix = max(ix, 0); iy = max(iy, 0);
    int cell = iy * GX + ix;
    g_pts[i] = make_float4(xn, yn, zn, p.w);
    g_cid[i] = cell;
    int b = i / NPTS;
    atomicAdd(&g_cnt[b * NC + cell], 1);
}

__global__ void k_scan(float* __restrict__ pilOut, int hasPillar) {
    __shared__ int wsC[32], wsO[32];
    int b = blockIdx.x;
    int tid = threadIdx.x;
    int lane = tid & 31, warp = tid >> 5;
    int cbase = b * NC + tid * CPT;
    int sumC = 0, sumO = 0;
    for (int j = 0; j < CPT; j++) { int v = g_cnt[cbase + j]; sumC += v; sumO += (v > 0); }
    int sC = sumC, sO = sumO;
    for (int d = 1; d < 32; d <<= 1) {
        int aC = __shfl_up_sync(0xffffffffu, sC, d);
        int aO = __shfl_up_sync(0xffffffffu, sO, d);
        if (lane >= d) { sC += aC; sO += aO; }
    }
    if (lane == 31) { wsC[warp] = sC; wsO[warp] = sO; }
    __syncthreads();
    if (warp == 0) {
        int vC = wsC[lane], vO = wsO[lane];
        for (int d = 1; d < 32; d <<= 1) {
            int aC = __shfl_up_sync(0xffffffffu, vC, d);
            int aO = __shfl_up_sync(0xffffffffu, vO, d);
            if (lane >= d) { vC += aC; vO += aO; }
        }
        wsC[lane] = vC; wsO[lane] = vO;
    }
    __syncthreads();
    int exC = sC - sumC + (warp ? wsC[warp - 1] : 0);
    int exO = sO - sumO + (warp ? wsO[warp - 1] : 0);
    for (int j = 0; j < CPT; j++) {
        int c = cbase + j;
        int v = g_cnt[c];
        g_off[c] = exC;
        g_sl[c]  = exO;
        if (v > 0) {
            if (hasPillar && exO < MAXPIL)
                pilOut[b * MAXPIL + exO] = (float)(tid * CPT + j);
            exO++;
        }
        exC += v;
    }
}

__global__ void k_scat() {
    int i = blockIdx.x * blockDim.x + threadIdx.x;
    if (i >= TOTPTS) return;
    int b = i / NPTS;
    int c = b * NC + g_cid[i];
    int pos = g_off[c] + atomicAdd(&g_fl[c], 1);
    if (pos < NPTS) g_lst[b * NPTS + pos] = i - b * NPTS;
}

__global__ void k_emit(float* __restrict__ out) {
    int i = blockIdx.x * blockDim.x + threadIdx.x;
    if (i >= TOTPTS) return;
    int b  = i / NPTS;
    int li = i - b * NPTS;
    int cell = g_cid[i];
    int c = b * NC + cell;
    int slot = g_sl[c];
    if (slot >= MAXPIL) return;
    int n = g_cnt[c];
    int lb = b * NPTS + g_off[c];
    int pb = b * NPTS;
    int rank = 0;
    double sx = 0.0, sy = 0.0, sz = 0.0;
    for (int t = 0; t < n; t++) {
        int pj = g_lst[lb + t];
        rank += (pj < li);
        float4 q = g_pts[pb + pj];
        sx += (double)q.x; sy += (double)q.y; sz += (double)q.z;
    }
    if (rank >= MAXPT) return;
    double dn = (double)n;
    float mx = (float)(sx / dn);
    float my = (float)(sy / dn);
    float mz = (float)(sz / dn);
    float4 p = g_pts[i];
    const float WHN = whn_const();
    float cx = __fadd_rn(__fadd_rn(-1.0f, __fmul_rn((float)(cell % GX), WHN)), __fmul_rn(WHN, 0.5f));
    float cy = __fadd_rn(__fadd_rn(-1.0f, __fmul_rn((float)(cell / GX), WHN)), __fmul_rn(WHN, 0.5f));
    float* o = out + ((size_t)(b * MAXPIL + slot) * MAXPT + rank) * 9;
    o[0] = p.x; o[1] = p.y; o[2] = p.z; o[3] = p.w;
    o[4] = fabsf(__fadd_rn(p.x, -mx));
    o[5] = fabsf(__fadd_rn(p.y, -my));
    o[6] = fabsf(__fadd_rn(p.z, -mz));
    o[7] = __fadd_rn(cx, -p.x);
    o[8] = __fadd_rn(cy, -p.y);
}

extern "C" void kernel_launch(void* const* d_in, const int* in_sizes, int n_in,
                              void* d_out, int out_size) {
    const float* in = (const float*)d_in[0];
    float* out = (float*)d_out;
    const long long FEAT = (long long)BATCH * MAXPIL * MAXPT * 9;
    int hasPillar = ((long long)out_size >= FEAT + (long long)BATCH * MAXPIL);
    float* pilOut = out + FEAT;

    int n4 = out_size / 4;
    int ntail = out_size - n4 * 4;
    k_zfill<<<2048, 256>>>((float4*)d_out, n4, out + (size_t)n4 * 4, ntail);
    k_aux<<<512, 256>>>(pilOut, hasPillar);
    k_prep<<<(TOTPTS + 255) / 256, 256>>>(in);
    k_scan<<<BATCH, SCANTH>>>(pilOut, hasPillar);
    k_scat<<<(TOTPTS + 255) / 256, 256>>>();
    k_emit<<<(TOTPTS + 255) / 256, 256>>>(out);
}

// round 12
// speedup vs baseline: 3.8651x; 2.3625x over previous
#include <cuda_runtime.h>
#include <math.h>

#define BATCH   4
#define NPTS    50000
#define GX      640
#define NC      (GX*GX)
#define MAXPIL  12000
#define MAXPT   100
#define TOTPTS  (BATCH*NPTS)
#define TOTCELL (BATCH*NC)
#define CB      2048               // cells per scan block
#define NBB     (NC/CB)            // 200 blocks per batch
#define NBLK    (BATCH*NBB)        // 800 scan blocks

__device__ float4 g_pts[TOTPTS];
__device__ int    g_cid[TOTPTS];
__device__ int    g_cnt[TOTCELL];
__device__ int    g_off[TOTCELL];
__device__ int    g_sl[TOTCELL];
__device__ int    g_fl[TOTCELL];
__device__ int    g_lst[TOTPTS];
__device__ int    g_bsC[NBLK];
__device__ int    g_bsO[NBLK];

// f32(0.32f/102.4f) = 0.0031249998044222593f (0x3B4CCCCC)
__device__ __forceinline__ float whn_const() {
    return __fdiv_rn(__fmul_rn(2.0f, 0.16f), 102.4f);
}
// fl32(1 / WH_N) = 320.000030517578125f (0x43A00001)
#define INV_WHN 320.000030517578125f

__global__ void k_zfill(float4* __restrict__ o4, int n4, float* __restrict__ tail, int ntail) {
    int i = blockIdx.x * blockDim.x + threadIdx.x;
    int stride = gridDim.x * blockDim.x;
    float4 z = make_float4(0.f, 0.f, 0.f, 0.f);
    for (; i < n4; i += stride) o4[i] = z;
    if (blockIdx.x == 0 && threadIdx.x < ntail) tail[threadIdx.x] = 0.f;
}

__global__ void k_aux(float* po, int hasPillar) {
    int i = blockIdx.x * blockDim.x + threadIdx.x;
    int stride = gridDim.x * blockDim.x;
    for (int j = i; j < TOTCELL; j += stride) { g_cnt[j] = 0; g_fl[j] = 0; }
    if (hasPillar)
        for (int j = i; j < BATCH * MAXPIL; j += stride) po[j] = -1.0f;
}

__global__ void k_prep(const float* __restrict__ in) {
    int i = blockIdx.x * blockDim.x + threadIdx.x;
    if (i >= TOTPTS) return;
    float4 p = reinterpret_cast<const float4*>(in)[i];
    float xn = __fadd_rn(__fmul_rn(__fadd_rn(p.x, 51.2f), 0.01953125f), -1.0f);
    float yn = __fadd_rn(__fmul_rn(__fadd_rn(p.y, 51.2f), 0.01953125f), -1.0f);
    float zn = __fadd_rn(__fmul_rn(__fadd_rn(p.z,  5.0f), 0.25f),       -1.0f);
    float tx = __fmul_rn(__fadd_rn(xn, 1.0f), INV_WHN);
    float ty = __fmul_rn(__fadd_rn(yn, 1.0f), INV_WHN);
    int ix = (int)fminf(floorf(tx), 639.0f);
    int iy = (int)fminf(floorf(ty), 639.0f);
    ix = max(ix, 0); iy = max(iy, 0);
    int cell = iy * GX + ix;
    g_pts[i] = make_float4(xn, yn, zn, p.w);
    g_cid[i] = cell;
    int b = i / NPTS;
    atomicAdd(&g_cnt[b * NC + cell], 1);
}

// Pass 1: per-block totals (coalesced reads). pack = count | (occ<<16).
__global__ void k_scan1() {
    __shared__ int red[256];
    int blk = blockIdx.x, tid = threadIdx.x;
    int base = blk * CB;
    int pk = 0;
#pragma unroll
    for (int k = 0; k < 8; k++) {
        int v = g_cnt[base + k * 256 + tid];
        pk += v + ((v > 0) << 16);
    }
    red[tid] = pk; __syncthreads();
    for (int s = 128; s > 0; s >>= 1) {
        if (tid < s) red[tid] += red[tid + s];
        __syncthreads();
    }
    if (tid == 0) { g_bsC[blk] = red[0] & 0xFFFF; g_bsO[blk] = red[0] >> 16; }
}

// Pass 2: exclusive scan of 800 partials, reset at batch boundaries.
__global__ void k_scan2() {
    if (threadIdx.x == 0) {
        int rc = 0, ro = 0;
        for (int blk = 0; blk < NBLK; blk++) {
            if (blk % NBB == 0) { rc = 0; ro = 0; }
            int tc = g_bsC[blk], to = g_bsO[blk];
            g_bsC[blk] = rc; g_bsO[blk] = ro;
            rc += tc; ro += to;
        }
    }
}

// Pass 3: block-local ordered dual prefix via smem; coalesced in/out.
__global__ void k_scan3(float* __restrict__ pilOut, int hasPillar) {
    __shared__ int s1[CB];   // counts -> g_off values
    __shared__ int s2[CB];   // -> g_sl values
    __shared__ int ws[8];
    int blk = blockIdx.x, tid = threadIdx.x;
    int lane = tid & 31, warp = tid >> 5;
    int base = blk * CB;
    int batch = blk / NBB;

#pragma unroll
    for (int k = 0; k < 8; k++) s1[k * 256 + tid] = g_cnt[base + k * 256 + tid];
    __syncthreads();

    // thread-local sums over its 8 ordered cells [tid*8, tid*8+8)
    int pk = 0;
#pragma unroll
    for (int j = 0; j < 8; j++) {
        int v = s1[tid * 8 + j];
        pk += v + ((v > 0) << 16);
    }
    // inclusive scan of pk over 256 threads
    int sp = pk;
    for (int d = 1; d < 32; d <<= 1) {
        int a = __shfl_up_sync(0xffffffffu, sp, d);
        if (lane >= d) sp += a;
    }
    if (lane == 31) ws[warp] = sp;
    __syncthreads();
    if (warp == 0 && lane < 8) {
        int v = ws[lane];
        for (int d = 1; d < 8; d <<= 1) {
            int a = __shfl_up_sync(0xffu, v, d);
            if (lane >= d) v += a;
        }
        ws[lane] = v;
    }
    __syncthreads();
    int ex = sp - pk + (warp ? ws[warp - 1] : 0);
    int exC = g_bsC[blk] + (ex & 0xFFFF);
    int exO = g_bsO[blk] + (ex >> 16);

#pragma unroll
    for (int j = 0; j < 8; j++) {
        int idx = tid * 8 + j;
        int v = s1[idx];
        s1[idx] = exC;
        s2[idx] = exO;
        if (v > 0) {
            if (hasPillar && exO < MAXPIL)
                pilOut[batch * MAXPIL + exO] = (float)(base + idx - batch * NC);
            exO++;
        }
        exC += v;
    }
    __syncthreads();
#pragma unroll
    for (int k = 0; k < 8; k++) {
        g_off[base + k * 256 + tid] = s1[k * 256 + tid];
        g_sl [base + k * 256 + tid] = s2[k * 256 + tid];
    }
}

__global__ void k_scat() {
    int i = blockIdx.x * blockDim.x + threadIdx.x;
    if (i >= TOTPTS) return;
    int b = i / NPTS;
    int c = b * NC + g_cid[i];
    int pos = g_off[c] + atomicAdd(&g_fl[c], 1);
    if (pos < NPTS) g_lst[b * NPTS + pos] = i - b * NPTS;
}

__global__ void k_emit(float* __restrict__ out) {
    int i = blockIdx.x * blockDim.x + threadIdx.x;
    if (i >= TOTPTS) return;
    int b  = i / NPTS;
    int li = i - b * NPTS;
    int cell = g_cid[i];
    int c = b * NC + cell;
    int slot = g_sl[c];
    if (slot >= MAXPIL) return;
    int n = g_cnt[c];
    int lb = b * NPTS + g_off[c];
    int pb = b * NPTS;
    int rank = 0;
    double sx = 0.0, sy = 0.0, sz = 0.0;
    for (int t = 0; t < n; t++) {
        int pj = g_lst[lb + t];
        rank += (pj < li);
        float4 q = g_pts[pb + pj];
        sx += (double)q.x; sy += (double)q.y; sz += (double)q.z;
    }
    if (rank >= MAXPT) return;
    double dn = (double)n;
    float mx = (float)(sx / dn);
    float my = (float)(sy / dn);
    float mz = (float)(sz / dn);
    float4 p = g_pts[i];
    const float WHN = whn_const();
    float cx = __fadd_rn(__fadd_rn(-1.0f, __fmul_rn((float)(cell % GX), WHN)), __fmul_rn(WHN, 0.5f));
    float cy = __fadd_rn(__fadd_rn(-1.0f, __fmul_rn((float)(cell / GX), WHN)), __fmul_rn(WHN, 0.5f));
    float* o = out + ((size_t)(b * MAXPIL + slot) * MAXPT + rank) * 9;
    o[0] = p.x; o[1] = p.y; o[2] = p.z; o[3] = p.w;
    o[4] = fabsf(__fadd_rn(p.x, -mx));
    o[5] = fabsf(__fadd_rn(p.y, -my));
    o[6] = fabsf(__fadd_rn(p.z, -mz));
    o[7] = __fadd_rn(cx, -p.x);
    o[8] = __fadd_rn(cy, -p.y);
}

extern "C" void kernel_launch(void* const* d_in, const int* in_sizes, int n_in,
                              void* d_out, int out_size) {
    const float* in = (const float*)d_in[0];
    float* out = (float*)d_out;
    const long long FEAT = (long long)BATCH * MAXPIL * MAXPT * 9;
    int hasPillar = ((long long)out_size >= FEAT + (long long)BATCH * MAXPIL);
    float* pilOut = out + FEAT;

    int n4 = out_size / 4;
    int ntail = out_size - n4 * 4;
    k_zfill<<<2048, 256>>>((float4*)d_out, n4, out + (size_t)n4 * 4, ntail);
    k_aux<<<1024, 256>>>(pilOut, hasPillar);
    k_prep<<<(TOTPTS + 255) / 256, 256>>>(in);
    k_scan1<<<NBLK, 256>>>();
    k_scan2<<<1, 32>>>();
    k_scan3<<<NBLK, 256>>>(pilOut, hasPillar);
    k_scat<<<(TOTPTS + 255) / 256, 256>>>();
    k_emit<<<(TOTPTS + 255) / 256, 256>>>(out);
}

// round 13
// speedup vs baseline: 12.7727x; 3.3047x over previous
#include <cuda_runtime.h>
#include <math.h>

#define BATCH   4
#define NPTS    50000
#define GX      640
#define NC      (GX*GX)
#define MAXPIL  12000
#define MAXPT   100
#define TOTPTS  (BATCH*NPTS)
#define TOTCELL (BATCH*NC)
#define CB      2048               // cells per scan block
#define NBB     (NC/CB)            // 200 blocks per batch
#define NBLK    (BATCH*NBB)        // 800 scan blocks

__device__ float4 g_pts[TOTPTS];
__device__ int    g_cid[TOTPTS];
__device__ int    g_cnt[TOTCELL];
__device__ int    g_off[TOTCELL];
__device__ int    g_sl[TOTCELL];
__device__ int    g_fl[TOTCELL];
__device__ int    g_lst[TOTPTS];
__device__ int    g_bsC[NBLK];
__device__ int    g_bsO[NBLK];

// f32(0.32f/102.4f) = 0.0031249998044222593f (0x3B4CCCCC)
__device__ __forceinline__ float whn_const() {
    return __fdiv_rn(__fmul_rn(2.0f, 0.16f), 102.4f);
}
// fl32(1 / WH_N) = 320.000030517578125f (0x43A00001)
#define INV_WHN 320.000030517578125f

// Zero output + clear scratch + fill pillar output, one streaming kernel.
__global__ void k_zfill(float4* __restrict__ o4, int n4, float* __restrict__ tail, int ntail,
                        float* __restrict__ po, int hasPillar) {
    int i = blockIdx.x * blockDim.x + threadIdx.x;
    int stride = gridDim.x * blockDim.x;
    float4 z = make_float4(0.f, 0.f, 0.f, 0.f);
    for (int j = i; j < n4; j += stride) o4[j] = z;
    for (int j = i; j < TOTCELL; j += stride) { g_cnt[j] = 0; g_fl[j] = 0; }
    if (hasPillar)
        for (int j = i; j < BATCH * MAXPIL; j += stride) po[j] = -1.0f;
    if (blockIdx.x == 0 && threadIdx.x < ntail) tail[threadIdx.x] = 0.f;
}

__global__ void k_prep(const float* __restrict__ in) {
    int i = blockIdx.x * blockDim.x + threadIdx.x;
    if (i >= TOTPTS) return;
    float4 p = reinterpret_cast<const float4*>(in)[i];
    float xn = __fadd_rn(__fmul_rn(__fadd_rn(p.x, 51.2f), 0.01953125f), -1.0f);
    float yn = __fadd_rn(__fmul_rn(__fadd_rn(p.y, 51.2f), 0.01953125f), -1.0f);
    float zn = __fadd_rn(__fmul_rn(__fadd_rn(p.z,  5.0f), 0.25f),       -1.0f);
    float tx = __fmul_rn(__fadd_rn(xn, 1.0f), INV_WHN);
    float ty = __fmul_rn(__fadd_rn(yn, 1.0f), INV_WHN);
    int ix = (int)fminf(floorf(tx), 639.0f);
    int iy = (int)fminf(floorf(ty), 639.0f);
    ix = max(ix, 0); iy = max(iy, 0);
    int cell = iy * GX + ix;
    g_pts[i] = make_float4(xn, yn, zn, p.w);
    g_cid[i] = cell;
    int b = i / NPTS;
    atomicAdd(&g_cnt[b * NC + cell], 1);
}

// Pass 1: per-block totals (coalesced reads). pack = count | (occ<<16).
__global__ void k_scan1() {
    __shared__ int red[256];
    int blk = blockIdx.x, tid = threadIdx.x;
    int base = blk * CB;
    int pk = 0;
#pragma unroll
    for (int k = 0; k < 8; k++) {
        int v = g_cnt[base + k * 256 + tid];
        pk += v + ((v > 0) << 16);
    }
    red[tid] = pk; __syncthreads();
    for (int s = 128; s > 0; s >>= 1) {
        if (tid < s) red[tid] += red[tid + s];
        __syncthreads();
    }
    if (tid == 0) { g_bsC[blk] = red[0] & 0xFFFF; g_bsO[blk] = red[0] >> 16; }
}

// Pass 2: parallel segmented exclusive scan of the 800 partials (segments = batches).
__global__ void k_scan2() {
    __shared__ int s[1024];
    int tid = threadIdx.x;
    int v = 0;
    if (tid < NBLK) v = g_bsC[tid] | (g_bsO[tid] << 16);
    s[tid] = v;
    __syncthreads();
    int seg = tid / NBB;
#pragma unroll
    for (int d = 1; d < 1024; d <<= 1) {
        int add = 0;
        if (tid >= d && (tid - d) / NBB == seg) add = s[tid - d];
        __syncthreads();
        s[tid] += add;
        __syncthreads();
    }
    if (tid < NBLK) {
        int ex = s[tid] - v;   // exclusive within segment; packed fields independent
        g_bsC[tid] = ex & 0xFFFF;
        g_bsO[tid] = ex >> 16;
    }
}

// Pass 3: block-local ordered dual prefix via smem; coalesced in/out.
__global__ void k_scan3(float* __restrict__ pilOut, int hasPillar) {
    __shared__ int s1[CB];
    __shared__ int s2[CB];
    __shared__ int ws[8];
    int blk = blockIdx.x, tid = threadIdx.x;
    int lane = tid & 31, warp = tid >> 5;
    int base = blk * CB;
    int batch = blk / NBB;

#pragma unroll
    for (int k = 0; k < 8; k++) s1[k * 256 + tid] = g_cnt[base + k * 256 + tid];
    __syncthreads();

    int pk = 0;
#pragma unroll
    for (int j = 0; j < 8; j++) {
        int v = s1[tid * 8 + j];
        pk += v + ((v > 0) << 16);
    }
    int sp = pk;
    for (int d = 1; d < 32; d <<= 1) {
        int a = __shfl_up_sync(0xffffffffu, sp, d);
        if (lane >= d) sp += a;
    }
    if (lane == 31) ws[warp] = sp;
    __syncthreads();
    if (warp == 0 && lane < 8) {
        int v = ws[lane];
        for (int d = 1; d < 8; d <<= 1) {
            int a = __shfl_up_sync(0xffu, v, d);
            if (lane >= d) v += a;
        }
        ws[lane] = v;
    }
    __syncthreads();
    int ex = sp - pk + (warp ? ws[warp - 1] : 0);
    int exC = g_bsC[blk] + (ex & 0xFFFF);
    int exO = g_bsO[blk] + (ex >> 16);

#pragma unroll
    for (int j = 0; j < 8; j++) {
        int idx = tid * 8 + j;
        int v = s1[idx];
        s1[idx] = exC;
        s2[idx] = exO;
        if (v > 0) {
            if (hasPillar && exO < MAXPIL)
                pilOut[batch * MAXPIL + exO] = (float)(base + idx - batch * NC);
            exO++;
        }
        exC += v;
    }
    __syncthreads();
#pragma unroll
    for (int k = 0; k < 8; k++) {
        g_off[base + k * 256 + tid] = s1[k * 256 + tid];
        g_sl [base + k * 256 + tid] = s2[k * 256 + tid];
    }
}

__global__ void k_scat() {
    int i = blockIdx.x * blockDim.x + threadIdx.x;
    if (i >= TOTPTS) return;
    int b = i / NPTS;
    int c = b * NC + g_cid[i];
    int pos = g_off[c] + atomicAdd(&g_fl[c], 1);
    if (pos < NPTS) g_lst[b * NPTS + pos] = i - b * NPTS;
}

__global__ void k_emit(float* __restrict__ out) {
    int i = blockIdx.x * blockDim.x + threadIdx.x;
    if (i >= TOTPTS) return;
    int b  = i / NPTS;
    int li = i - b * NPTS;
    int cell = g_cid[i];
    int c = b * NC + cell;
    int slot = g_sl[c];
    if (slot >= MAXPIL) return;
    int n = g_cnt[c];
    int lb = b * NPTS + g_off[c];
    int pb = b * NPTS;
    int rank = 0;
    double sx = 0.0, sy = 0.0, sz = 0.0;
    for (int t = 0; t < n; t++) {
        int pj = g_lst[lb + t];
        rank += (pj < li);
        float4 q = g_pts[pb + pj];
        sx += (double)q.x; sy += (double)q.y; sz += (double)q.z;
    }
    if (rank >= MAXPT) return;
    double dn = (double)n;
    float mx = (float)(sx / dn);
    float my = (float)(sy / dn);
    float mz = (float)(sz / dn);
    float4 p = g_pts[i];
    const float WHN = whn_const();
    float cx = __fadd_rn(__fadd_rn(-1.0f, __fmul_rn((float)(cell % GX), WHN)), __fmul_rn(WHN, 0.5f));
    float cy = __fadd_rn(__fadd_rn(-1.0f, __fmul_rn((float)(cell / GX), WHN)), __fmul_rn(WHN, 0.5f));
    float* o = out + ((size_t)(b * MAXPIL + slot) * MAXPT + rank) * 9;
    o[0] = p.x; o[1] = p.y; o[2] = p.z; o[3] = p.w;
    o[4] = fabsf(__fadd_rn(p.x, -mx));
    o[5] = fabsf(__fadd_rn(p.y, -my));
    o[6] = fabsf(__fadd_rn(p.z, -mz));
    o[7] = __fadd_rn(cx, -p.x);
    o[8] = __fadd_rn(cy, -p.y);
}

extern "C" void kernel_launch(void* const* d_in, const int* in_sizes, int n_in,
                              void* d_out, int out_size) {
    const float* in = (const float*)d_in[0];
    float* out = (float*)d_out;
    const long long FEAT = (long long)BATCH * MAXPIL * MAXPT * 9;
    int hasPillar = ((long long)out_size >= FEAT + (long long)BATCH * MAXPIL);
    float* pilOut = out + FEAT;

    int n4 = out_size / 4;
    int ntail = out_size - n4 * 4;
    k_zfill<<<4096, 256>>>((float4*)d_out, n4, out + (size_t)n4 * 4, ntail, pilOut, hasPillar);
    k_prep<<<(TOTPTS + 255) / 256, 256>>>(in);
    k_scan1<<<NBLK, 256>>>();
    k_scan2<<<1, 1024>>>();
    k_scan3<<<NBLK, 256>>>(pilOut, hasPillar);
    k_scat<<<(TOTPTS + 255) / 256, 256>>>();
    k_emit<<<(TOTPTS + 255) / 256, 256>>>(out);
}

// round 14
// speedup vs baseline: 13.2863x; 1.0402x over previous
#include <cuda_runtime.h>
#include <math.h>

#define BATCH   4
#define NPTS    50000
#define GX      640
#define NC      (GX*GX)
#define MAXPIL  12000
#define MAXPT   100
#define TOTPTS  (BATCH*NPTS)
#define TOTCELL (BATCH*NC)
#define CB      2048               // cells per scan block
#define NBB     (NC/CB)            // 200 blocks per batch
#define NBLK    (BATCH*NBB)        // 800 scan blocks
#define FEATN   (BATCH*MAXPIL*MAXPT*9)   // 43,200,000 floats (divisible by 4)
#define PILN    (BATCH*MAXPIL)

__device__ float4 g_pts[TOTPTS];
__device__ int    g_cid[TOTPTS];
__device__ int    g_cnt[TOTCELL];
__device__ int    g_off[TOTCELL];
__device__ int    g_sl[TOTCELL];
__device__ int    g_fl[TOTCELL];
__device__ int    g_lst[TOTPTS];
__device__ int    g_bsC[NBLK];
__device__ int    g_bsO[NBLK];

// f32(0.32f/102.4f) = 0.0031249998044222593f (0x3B4CCCCC)
__device__ __forceinline__ float whn_const() {
    return __fdiv_rn(__fmul_rn(2.0f, 0.16f), 102.4f);
}
// fl32(1 / WH_N) = 320.000030517578125f (0x43A00001)
#define INV_WHN 320.000030517578125f

// Zero feature region (streaming stores), fill pillar region with -1,
// zero any residual tail, clear scratch. No overlapping writes -> race-free.
__global__ void k_zfill(float* __restrict__ out, int out_size, int hasPillar) {
    int i = blockIdx.x * blockDim.x + threadIdx.x;
    int stride = gridDim.x * blockDim.x;
    float4* o4 = (float4*)out;
    const int n4 = FEATN / 4;                 // 10,800,000
    float4 z = make_float4(0.f, 0.f, 0.f, 0.f);
    for (int j = i; j < n4; j += stride) __stcs(&o4[j], z);
    if (hasPillar) {
        float* po = out + FEATN;
        for (int j = i; j < PILN; j += stride) po[j] = -1.0f;
        for (int j = FEATN + PILN + i; j < out_size; j += stride) out[j] = 0.f;
    } else {
        for (int j = FEATN + i; j < out_size; j += stride) out[j] = 0.f;
    }
    for (int j = i; j < TOTCELL; j += stride) { g_cnt[j] = 0; g_fl[j] = 0; }
}

__global__ void k_prep(const float* __restrict__ in) {
    int i = blockIdx.x * blockDim.x + threadIdx.x;
    if (i >= TOTPTS) return;
    float4 p = reinterpret_cast<const float4*>(in)[i];
    float xn = __fadd_rn(__fmul_rn(__fadd_rn(p.x, 51.2f), 0.01953125f), -1.0f);
    float yn = __fadd_rn(__fmul_rn(__fadd_rn(p.y, 51.2f), 0.01953125f), -1.0f);
    float zn = __fadd_rn(__fmul_rn(__fadd_rn(p.z,  5.0f), 0.25f),       -1.0f);
    float tx = __fmul_rn(__fadd_rn(xn, 1.0f), INV_WHN);
    float ty = __fmul_rn(__fadd_rn(yn, 1.0f), INV_WHN);
    int ix = (int)fminf(floorf(tx), 639.0f);
    int iy = (int)fminf(floorf(ty), 639.0f);
    ix = max(ix, 0); iy = max(iy, 0);
    int cell = iy * GX + ix;
    g_pts[i] = make_float4(xn, yn, zn, p.w);
    g_cid[i] = cell;
    int b = i / NPTS;
    atomicAdd(&g_cnt[b * NC + cell], 1);
}

// Pass 1: per-block totals (coalesced). pack = count | (occ<<16).
__global__ void k_scan1() {
    __shared__ int red[256];
    int blk = blockIdx.x, tid = threadIdx.x;
    int base = blk * CB;
    int pk = 0;
#pragma unroll
    for (int k = 0; k < 8; k++) {
        int v = g_cnt[base + k * 256 + tid];
        pk += v + ((v > 0) << 16);
    }
    red[tid] = pk; __syncthreads();
    for (int s = 128; s > 0; s >>= 1) {
        if (tid < s) red[tid] += red[tid + s];
        __syncthreads();
    }
    if (tid == 0) { g_bsC[blk] = red[0] & 0xFFFF; g_bsO[blk] = red[0] >> 16; }
}

// Pass 2: parallel segmented exclusive scan of the 800 partials.
__global__ void k_scan2() {
    __shared__ int s[1024];
    int tid = threadIdx.x;
    int v = 0;
    if (tid < NBLK) v = g_bsC[tid] | (g_bsO[tid] << 16);
    s[tid] = v;
    __syncthreads();
    int seg = tid / NBB;
#pragma unroll
    for (int d = 1; d < 1024; d <<= 1) {
        int add = 0;
        if (tid >= d && (tid - d) / NBB == seg) add = s[tid - d];
        __syncthreads();
        s[tid] += add;
        __syncthreads();
    }
    if (tid < NBLK) {
        int ex = s[tid] - v;
        g_bsC[tid] = ex & 0xFFFF;
        g_bsO[tid] = ex >> 16;
    }
}

// Pass 3: block-local ordered dual prefix via smem; coalesced in/out.
__global__ void k_scan3(float* __restrict__ pilOut, int hasPillar) {
    __shared__ int s1[CB];
    __shared__ int s2[CB];
    __shared__ int ws[8];
    int blk = blockIdx.x, tid = threadIdx.x;
    int lane = tid & 31, warp = tid >> 5;
    int base = blk * CB;
    int batch = blk / NBB;

#pragma unroll
    for (int k = 0; k < 8; k++) s1[k * 256 + tid] = g_cnt[base + k * 256 + tid];
    __syncthreads();

    int pk = 0;
#pragma unroll
    for (int j = 0; j < 8; j++) {
        int v = s1[tid * 8 + j];
        pk += v + ((v > 0) << 16);
    }
    int sp = pk;
    for (int d = 1; d < 32; d <<= 1) {
        int a = __shfl_up_sync(0xffffffffu, sp, d);
        if (lane >= d) sp += a;
    }
    if (lane == 31) ws[warp] = sp;
    __syncthreads();
    if (warp == 0 && lane < 8) {
        int v = ws[lane];
        for (int d = 1; d < 8; d <<= 1) {
            int a = __shfl_up_sync(0xffu, v, d);
            if (lane >= d) v += a;
        }
        ws[lane] = v;
    }
    __syncthreads();
    int ex = sp - pk + (warp ? ws[warp - 1] : 0);
    int exC = g_bsC[blk] + (ex & 0xFFFF);
    int exO = g_bsO[blk] + (ex >> 16);

#pragma unroll
    for (int j = 0; j < 8; j++) {
        int idx = tid * 8 + j;
        int v = s1[idx];
        s1[idx] = exC;
        s2[idx] = exO;
        if (v > 0) {
            if (hasPillar && exO < MAXPIL)
                pilOut[batch * MAXPIL + exO] = (float)(base + idx - batch * NC);
            exO++;
        }
        exC += v;
    }
    __syncthreads();
#pragma unroll
    for (int k = 0; k < 8; k++) {
        g_off[base + k * 256 + tid] = s1[k * 256 + tid];
        g_sl [base + k * 256 + tid] = s2[k * 256 + tid];
    }
}

__global__ void k_scat() {
    int i = blockIdx.x * blockDim.x + threadIdx.x;
    if (i >= TOTPTS) return;
    int b = i / NPTS;
    int c = b * NC + g_cid[i];
    int pos = g_off[c] + atomicAdd(&g_fl[c], 1);
    if (pos < NPTS) g_lst[b * NPTS + pos] = i - b * NPTS;
}

__global__ void k_emit(float* __restrict__ out) {
    int i = blockIdx.x * blockDim.x + threadIdx.x;
    if (i >= TOTPTS) return;
    int b  = i / NPTS;
    int li = i - b * NPTS;
    int cell = g_cid[i];
    int c = b * NC + cell;
    int slot = g_sl[c];
    if (slot >= MAXPIL) return;
    int n = g_cnt[c];
    int lb = b * NPTS + g_off[c];
    int pb = b * NPTS;
    int rank = 0;
    double sx = 0.0, sy = 0.0, sz = 0.0;
    for (int t = 0; t < n; t++) {
        int pj = g_lst[lb + t];
        rank += (pj < li);
        float4 q = g_pts[pb + pj];
        sx += (double)q.x; sy += (double)q.y; sz += (double)q.z;
    }
    if (rank >= MAXPT) return;
    double dn = (double)n;
    float mx = (float)(sx / dn);
    float my = (float)(sy / dn);
    float mz = (float)(sz / dn);
    float4 p = g_pts[i];
    const float WHN = whn_const();
    float cx = __fadd_rn(__fadd_rn(-1.0f, __fmul_rn((float)(cell % GX), WHN)), __fmul_rn(WHN, 0.5f));
    float cy = __fadd_rn(__fadd_rn(-1.0f, __fmul_rn((float)(cell / GX), WHN)), __fmul_rn(WHN, 0.5f));
    float* o = out + ((size_t)(b * MAXPIL + slot) * MAXPT + rank) * 9;
    o[0] = p.x; o[1] = p.y; o[2] = p.z; o[3] = p.w;
    o[4] = fabsf(__fadd_rn(p.x, -mx));
    o[5] = fabsf(__fadd_rn(p.y, -my));
    o[6] = fabsf(__fadd_rn(p.z, -mz));
    o[7] = __fadd_rn(cx, -p.x);
    o[8] = __fadd_rn(cy, -p.y);
}

extern "C" void kernel_launch(void* const* d_in, const int* in_sizes, int n_in,
                              void* d_out, int out_size) {
    const float* in = (const float*)d_in[0];
    float* out = (float*)d_out;
    int hasPillar = ((long long)out_size >= (long long)FEATN + PILN);
    float* pilOut = out + FEATN;

    k_zfill<<<4096, 256>>>(out, out_size, hasPillar);
    k_prep<<<(TOTPTS + 255) / 256, 256>>>(in);
    k_scan1<<<NBLK, 256>>>();
    k_scan2<<<1, 1024>>>();
    k_scan3<<<NBLK, 256>>>(pilOut, hasPillar);
    k_scat<<<(TOTPTS + 255) / 256, 256>>>();
    k_emit<<<(TOTPTS + 255) / 256, 256>>>(out);
}